// round 14
// baseline (speedup 1.0000x reference)
#include <cuda_runtime.h>
#include <cuda_bf16.h>
#include <cstddef>

// Problem constants
#define BB 8
#define TT 16
#define HH 64
#define WW 64
#define CIN 32
#define FF 32
#define G4F 128
#define BN_EPS 1e-3f

typedef unsigned long long ull;

// ===== geometry: 32x16 tile, 256 threads, 2 px/thread (rows pr, pr+8) =====
#define TW 32
#define TH 16
#define IN_ROWS 18
#define IN_COLS 34
#define ROW_STRIDE (32 * IN_COLS)
#define SIN_FLOATS (IN_ROWS * ROW_STRIDE)     // 19584
#define SWBUF_FLOATS (4 * 32 * 32)            // 4096 (4 tap slots)
#define SBIAS_FLOATS 32
#define LS_SMEM ((SIN_FLOATS + SWBUF_FLOATS + SBIAS_FLOATS) * 4)  // 94848 -> 2 CTA/SM
#define LSTM_GRID 256

// ======================= device scratch (no allocs) ========================
// h state TRANSPOSED: [2][b][f][y][x]
__device__ float g_h[2][(size_t)BB * FF * HH * WW];
__device__ float g_c[(size_t)BB * HH * WW * FF];
__device__ unsigned g_bar[TT];

// ======================= helpers ===========================================
__device__ __forceinline__ float hsig(float x) {
    return __saturatef(fmaf(0.2f, x, 0.5f));
}
// fast tanh: exact at saturation (e -> inf/0), ~1e-6 rel elsewhere
__device__ __forceinline__ float ftanh(float x) {
    float e = __expf(2.f * x);
    return 1.f - 2.f / (e + 1.f);
}
__device__ __forceinline__ ull pack2(float v) {
    ull r;
    asm("mov.b64 %0, {%1, %1};" : "=l"(r) : "f"(v));
    return r;
}
__device__ __forceinline__ void ffma2(ull& d, ull a, ull b) {
    asm("fma.rn.f32x2 %0, %1, %2, %3;" : "=l"(d) : "l"(a), "l"(b), "l"(d));
}
__device__ __forceinline__ void unpack2(ull p, float& lo, float& hi) {
    asm("mov.b64 {%0, %1}, %2;" : "=f"(lo), "=f"(hi) : "l"(p));
}

// One 3x3 tap (dy,dx) over 32 cin for 2 pixels, 32 couts. (proven core)
__device__ __forceinline__ void conv_tap(
    const float* __restrict__ s_in, const float* __restrict__ wb,
    int pr, int px, int dy, int dx, ull* acc0, ull* acc1)
{
    const float* i0 = &s_in[(pr + dy) * ROW_STRIDE + (px + dx)];
    const float* i1 = i0 + 8 * ROW_STRIDE;
#pragma unroll 4
    for (int cin = 0; cin < 32; cin++) {
        ull v0 = pack2(i0[cin * IN_COLS]);
        ull v1 = pack2(i1[cin * IN_COLS]);
        const ulonglong2* w2 = (const ulonglong2*)(wb + cin * 32);
#pragma unroll
        for (int q = 0; q < 8; q++) {
            ulonglong2 w = w2[q];
            ffma2(acc0[q * 2 + 0], v0, w.x);
            ffma2(acc0[q * 2 + 1], v0, w.y);
            ffma2(acc1[q * 2 + 0], v1, w.x);
            ffma2(acc1[q * 2 + 1], v1, w.y);
        }
    }
}

// Gate-interleaved tap loader: smem col = g*8+j -> gmem cout = g*32+fc*8+j
__device__ __forceinline__ void load_tap_w(
    float* __restrict__ dst, const float* __restrict__ W, int kk, int fc, int tid)
{
    int cin = tid >> 3, col0 = (tid & 7) * 4;
    int cout0 = (col0 >> 3) * 32 + fc * 8 + (col0 & 7);
    float4 w = *(const float4*)&W[((size_t)(kk * CIN + cin)) * G4F + cout0];
    *(float4*)&dst[cin * 32 + col0] = w;
}

// One full conv phase (9 taps) with tap-PAIR double buffering: 5 syncs.
__device__ __forceinline__ void conv_phase(
    const float* __restrict__ W, const float* __restrict__ s_in,
    float* __restrict__ s_w, int fc, int tid, int pr, int px,
    ull* acc0, ull* acc1)
{
    load_tap_w(s_w + 0 * 1024, W, 0, fc, tid);
    load_tap_w(s_w + 1 * 1024, W, 1, fc, tid);
    __syncthreads();
#pragma unroll
    for (int k = 0; k < 4; k++) {
        const int ta = 2 * k, tb = 2 * k + 1;
        const int la = ta + 2, lb = tb + 2;
        if (la < 9) load_tap_w(s_w + (la & 3) * 1024, W, la, fc, tid);
        if (lb < 9) load_tap_w(s_w + (lb & 3) * 1024, W, lb, fc, tid);
        conv_tap(s_in, s_w + (ta & 3) * 1024, pr, px, ta / 3, ta % 3, acc0, acc1);
        conv_tap(s_in, s_w + (tb & 3) * 1024, pr, px, tb / 3, tb % 3, acc0, acc1);
        __syncthreads();
    }
    conv_tap(s_in, s_w + (8 & 3) * 1024, pr, px, 2, 2, acc0, acc1);
}

// x tile loader: [y][x][cin] gmem (NHWC), float4 along cin.
__device__ __forceinline__ void load_x_tile(
    float* __restrict__ s_in, const float* __restrict__ src,
    int ty0, int tx0, int tid)
{
    for (int j = tid; j < 612 * 8; j += 256) {
        int c4 = j & 7;
        int p  = j >> 3;
        int row = p / IN_COLS, col = p - row * IN_COLS;
        int gy = ty0 + row - 1, gx = tx0 + col - 1;
        float4 v = make_float4(0.f, 0.f, 0.f, 0.f);
        if ((unsigned)gy < (unsigned)HH && (unsigned)gx < (unsigned)WW)
            v = __ldg((const float4*)&src[((size_t)gy * WW + gx) * CIN + c4 * 4]);
        float* d = &s_in[(row * 32 + c4 * 4) * IN_COLS + col];
        d[0 * IN_COLS] = v.x;
        d[1 * IN_COLS] = v.y;
        d[2 * IN_COLS] = v.z;
        d[3 * IN_COLS] = v.w;
    }
}

// h tile loader from TRANSPOSED layout [f][y][x]: L1-bypassing float4 loads.
__device__ __forceinline__ void load_h_tile(
    float* __restrict__ s_in, const float* __restrict__ src,
    int ty0, int tx0, int tid)
{
    for (int j = tid; j < 18 * 32 * 8; j += 256) {
        int c4  = j & 7;
        int cin = (j >> 3) & 31;
        int row = j >> 8;
        int gy = ty0 + row - 1;
        int gx0 = tx0 + c4 * 4;
        float4 v = make_float4(0.f, 0.f, 0.f, 0.f);
        if ((unsigned)gy < (unsigned)HH)
            v = __ldcv((const float4*)&src[((size_t)cin * HH + gy) * WW + gx0]);
        float* d = &s_in[(row * 32 + cin) * IN_COLS + (c4 * 4 + 1)];
        d[0] = v.x; d[1] = v.y; d[2] = v.z; d[3] = v.w;
    }
    for (int j = tid; j < 18 * 32 * 2; j += 256) {
        int e   = j & 1;
        int cin = (j >> 1) & 31;
        int row = j >> 6;
        int gy = ty0 + row - 1;
        int gx = e ? (tx0 + 32) : (tx0 - 1);
        float v = 0.f;
        if ((unsigned)gy < (unsigned)HH && (unsigned)gx < (unsigned)WW)
            v = __ldcv(&src[((size_t)cin * HH + gy) * WW + gx]);
        s_in[(row * 32 + cin) * IN_COLS + (e ? 33 : 0)] = v;
    }
}

__global__ void bar_reset_kernel() {
    if (threadIdx.x < TT) g_bar[threadIdx.x] = 0u;
}

// ---------------------------------------------------------------------------
// Fully fused persistent ConvLSTM with barrier hiding:
//   epilogue(t) -> arrive(t) -> x-conv(t+1) -> wait(t) -> h-conv(t+1)
// The independent x-phase (~50us) absorbs barrier straggler stalls.
// grid 256 CTAs (2/SM), block 256, 2 px/thread, 10 syncs/step.
// ---------------------------------------------------------------------------
__global__ void __launch_bounds__(256, 2) convlstm_persistent(
    const float* __restrict__ x, const float* __restrict__ Wx,
    const float* __restrict__ Wh, const float* __restrict__ b,
    const float* __restrict__ gamma, const float* __restrict__ beta,
    const float* __restrict__ mmean, const float* __restrict__ mvar,
    float* __restrict__ out)
{
    extern __shared__ float sm[];
    float* s_in   = sm;
    float* s_w    = sm + SIN_FLOATS;
    float* s_bias = sm + SIN_FLOATS + SWBUF_FLOATS;

    const int cta  = blockIdx.x;
    const int tile = cta & 7;
    const int fc   = (cta >> 3) & 3;
    const int bb   = cta >> 5;
    const int tx0 = (tile & 1) * TW;
    const int ty0 = (tile >> 1) * TH;
    const int tid = threadIdx.x;
    const int px = tid & 31, pr = tid >> 5;
    const int gx = tx0 + px;
    const int gy0 = ty0 + pr;

    // BN constants (loop-invariant)
    float inv[8], off[8];
#pragma unroll
    for (int j = 0; j < 8; j++) {
        int f = fc * 8 + j;
        inv[j] = gamma[f] * rsqrtf(mvar[f] + BN_EPS);
        off[j] = beta[f] - mmean[f] * inv[j];
    }
    // interleaved bias: s_bias[col] = b[(col>>3)*32 + fc*8 + (col&7)]
    if (tid < 32)
        s_bias[tid] = b[(tid >> 3) * 32 + fc * 8 + (tid & 7)];
    __syncthreads();

    ull acc0[16], acc1[16];

    // prologue: x-phase for t=0
#pragma unroll
    for (int m = 0; m < 16; m++) {
        ull bv = *(const ull*)&s_bias[2 * m];
        acc0[m] = bv; acc1[m] = bv;
    }
    load_x_tile(s_in, x + (size_t)(bb * TT + 0) * HH * WW * CIN, ty0, tx0, tid);
    conv_phase(Wx, s_in, s_w, fc, tid, pr, px, acc0, acc1);

    for (int t = 0; t < TT; t++) {
        if (t > 0) {
            // wait for h_{t-1} (barrier t-1); mostly satisfied already
            if (tid == 0) {
                while (*((volatile unsigned*)&g_bar[t - 1]) < (unsigned)LSTM_GRID)
                    __nanosleep(32);
            }
            __syncthreads();
            __threadfence();
            // h-phase: reuse s_in (x-conv reads finished; the sync above orders)
            const float* hin = g_h[(t + 1) & 1] + (size_t)bb * FF * HH * WW;
            load_h_tile(s_in, hin, ty0, tx0, tid);
            conv_phase(Wh, s_in, s_w, fc, tid, pr, px, acc0, acc1);
        }

        // ---- epilogue: gates, c/h update, BN, stores ----
        float a0[32], a1[32];
#pragma unroll
        for (int m = 0; m < 16; m++) {
            unpack2(acc0[m], a0[2 * m], a0[2 * m + 1]);
            unpack2(acc1[m], a1[2 * m], a1[2 * m + 1]);
        }

        float* hbase = g_h[t & 1] + (size_t)bb * FF * HH * WW;

#pragma unroll
        for (int p = 0; p < 2; p++) {
            const float* a = p ? a1 : a0;
            const int gy = gy0 + p * 8;
            const size_t pix   = (size_t)bb * HH * WW + (size_t)gy * WW + gx;
            const size_t frame = (size_t)(bb * TT + t) * HH * WW + (size_t)gy * WW + gx;
            float* cst = &g_c[pix * FF + fc * 8];
            float* op  = &out[frame * FF + fc * 8];

            float coldv[8] = {0,0,0,0,0,0,0,0};
            if (t > 0) {
                float4 c0 = ((const float4*)cst)[0];
                float4 c1 = ((const float4*)cst)[1];
                coldv[0]=c0.x; coldv[1]=c0.y; coldv[2]=c0.z; coldv[3]=c0.w;
                coldv[4]=c1.x; coldv[5]=c1.y; coldv[6]=c1.z; coldv[7]=c1.w;
            }

            float cv[8], hv[8], ov[8];
#pragma unroll
            for (int j = 0; j < 8; j++) {
                float gi = hsig(a[0 * 8 + j]);
                float gf = hsig(a[1 * 8 + j]);
                float gc = a[2 * 8 + j];
                float go = hsig(a[3 * 8 + j]);
                float cn = gf * coldv[j] + gi * ftanh(gc);
                float h  = go * ftanh(cn);
                cv[j] = cn; hv[j] = h;
                ov[j] = fmaf(h, inv[j], off[j]);
            }
            ((float4*)cst)[0] = make_float4(cv[0], cv[1], cv[2], cv[3]);
            ((float4*)cst)[1] = make_float4(cv[4], cv[5], cv[6], cv[7]);
#pragma unroll
            for (int j = 0; j < 8; j++) {
                int f = fc * 8 + j;
                hbase[((size_t)f * HH + gy) * WW + gx] = hv[j];
            }
            ((float4*)op)[0] = make_float4(ov[0], ov[1], ov[2], ov[3]);
            ((float4*)op)[1] = make_float4(ov[4], ov[5], ov[6], ov[7]);
        }

        if (t < TT - 1) {
            // arrive: publish h_t
            __threadfence();
            __syncthreads();
            if (tid == 0) atomicAdd(&g_bar[t], 1u);

            // overlap: x-phase for t+1 (independent of h_t)
#pragma unroll
            for (int m = 0; m < 16; m++) {
                ull bv = *(const ull*)&s_bias[2 * m];
                acc0[m] = bv; acc1[m] = bv;
            }
            load_x_tile(s_in, x + (size_t)(bb * TT + t + 1) * HH * WW * CIN,
                        ty0, tx0, tid);
            conv_phase(Wx, s_in, s_w, fc, tid, pr, px, acc0, acc1);
        }
    }
}

// ===========================================================================
extern "C" void kernel_launch(void* const* d_in, const int* in_sizes, int n_in,
                              void* d_out, int out_size)
{
    const float* x     = (const float*)d_in[0];
    const float* Wx    = (const float*)d_in[1];
    const float* Wh    = (const float*)d_in[2];
    const float* b     = (const float*)d_in[3];
    const float* gamma = (const float*)d_in[4];
    const float* beta  = (const float*)d_in[5];
    const float* mmean = (const float*)d_in[6];
    const float* mvar  = (const float*)d_in[7];
    float* out = (float*)d_out;

    cudaFuncSetAttribute(convlstm_persistent,
        cudaFuncAttributeMaxDynamicSharedMemorySize, LS_SMEM);

    bar_reset_kernel<<<1, 32>>>();
    convlstm_persistent<<<LSTM_GRID, 256, LS_SMEM>>>(
        x, Wx, Wh, b, gamma, beta, mmean, mvar, out);
}

// round 15
// speedup vs baseline: 1.0908x; 1.0908x over previous
#include <cuda_runtime.h>
#include <cuda_bf16.h>
#include <cstddef>

// Problem constants
#define BB 8
#define TT 16
#define HH 64
#define WW 64
#define CIN 32
#define FF 32
#define G4F 128
#define BN_EPS 1e-3f

typedef unsigned long long ull;

// ===== geometry: 32x16 tile, 256 threads, 2 px/thread (rows pr, pr+8) =====
#define TW 32
#define TH 16
#define IN_ROWS 18
#define IN_COLS 34
#define ROW_STRIDE (32 * IN_COLS)
#define SIN_FLOATS (IN_ROWS * ROW_STRIDE)     // 19584
#define SWBUF_FLOATS (4 * 32 * 32)            // 4096 (4 tap slots)
#define SBIAS_FLOATS 32
#define LS_SMEM ((SIN_FLOATS + SWBUF_FLOATS + SBIAS_FLOATS) * 4)  // 94848 -> 2 CTA/SM
#define LSTM_GRID 256

// ======================= device scratch (no allocs) ========================
// h state TRANSPOSED: [2][b][f][y][x]
__device__ float g_h[2][(size_t)BB * FF * HH * WW];
__device__ float g_c[(size_t)BB * HH * WW * FF];
__device__ unsigned g_bar[TT];

// ======================= helpers ===========================================
__device__ __forceinline__ float hsig(float x) {
    return __saturatef(fmaf(0.2f, x, 0.5f));
}
__device__ __forceinline__ ull pack2(float v) {
    ull r;
    asm("mov.b64 %0, {%1, %1};" : "=l"(r) : "f"(v));
    return r;
}
__device__ __forceinline__ void ffma2(ull& d, ull a, ull b) {
    asm("fma.rn.f32x2 %0, %1, %2, %3;" : "=l"(d) : "l"(a), "l"(b), "l"(d));
}
__device__ __forceinline__ void unpack2(ull p, float& lo, float& hi) {
    asm("mov.b64 {%0, %1}, %2;" : "=f"(lo), "=f"(hi) : "l"(p));
}

// One 3x3 tap (dy,dx) over 32 cin for 2 pixels, 32 couts. (proven core)
__device__ __forceinline__ void conv_tap(
    const float* __restrict__ s_in, const float* __restrict__ wb,
    int pr, int px, int dy, int dx, ull* acc0, ull* acc1)
{
    const float* i0 = &s_in[(pr + dy) * ROW_STRIDE + (px + dx)];
    const float* i1 = i0 + 8 * ROW_STRIDE;
#pragma unroll 4
    for (int cin = 0; cin < 32; cin++) {
        ull v0 = pack2(i0[cin * IN_COLS]);
        ull v1 = pack2(i1[cin * IN_COLS]);
        const ulonglong2* w2 = (const ulonglong2*)(wb + cin * 32);
#pragma unroll
        for (int q = 0; q < 8; q++) {
            ulonglong2 w = w2[q];
            ffma2(acc0[q * 2 + 0], v0, w.x);
            ffma2(acc0[q * 2 + 1], v0, w.y);
            ffma2(acc1[q * 2 + 0], v1, w.x);
            ffma2(acc1[q * 2 + 1], v1, w.y);
        }
    }
}

// Gate-interleaved tap loader: smem col = g*8+j -> gmem cout = g*32+fc*8+j
__device__ __forceinline__ void load_tap_w(
    float* __restrict__ dst, const float* __restrict__ W, int kk, int fc, int tid)
{
    int cin = tid >> 3, col0 = (tid & 7) * 4;
    int cout0 = (col0 >> 3) * 32 + fc * 8 + (col0 & 7);
    float4 w = *(const float4*)&W[((size_t)(kk * CIN + cin)) * G4F + cout0];
    *(float4*)&dst[cin * 32 + col0] = w;
}

// One full conv phase (9 taps), tap-PAIR double buffered: 5 syncs.
__device__ __forceinline__ void conv_phase(
    const float* __restrict__ W, const float* __restrict__ s_in,
    float* __restrict__ s_w, int fc, int tid, int pr, int px,
    ull* acc0, ull* acc1)
{
    load_tap_w(s_w + 0 * 1024, W, 0, fc, tid);
    load_tap_w(s_w + 1 * 1024, W, 1, fc, tid);
    __syncthreads();
#pragma unroll
    for (int k = 0; k < 4; k++) {
        const int ta = 2 * k, tb = 2 * k + 1;
        const int la = ta + 2, lb = tb + 2;
        if (la < 9) load_tap_w(s_w + (la & 3) * 1024, W, la, fc, tid);
        if (lb < 9) load_tap_w(s_w + (lb & 3) * 1024, W, lb, fc, tid);
        conv_tap(s_in, s_w + (ta & 3) * 1024, pr, px, ta / 3, ta % 3, acc0, acc1);
        conv_tap(s_in, s_w + (tb & 3) * 1024, pr, px, tb / 3, tb % 3, acc0, acc1);
        __syncthreads();
    }
    conv_tap(s_in, s_w + (8 & 3) * 1024, pr, px, 2, 2, acc0, acc1);
}

// x tile loader: [y][x][cin] gmem (NHWC), float4 along cin.
__device__ __forceinline__ void load_x_tile(
    float* __restrict__ s_in, const float* __restrict__ src,
    int ty0, int tx0, int tid)
{
    for (int j = tid; j < 612 * 8; j += 256) {
        int c4 = j & 7;
        int p  = j >> 3;
        int row = p / IN_COLS, col = p - row * IN_COLS;
        int gy = ty0 + row - 1, gx = tx0 + col - 1;
        float4 v = make_float4(0.f, 0.f, 0.f, 0.f);
        if ((unsigned)gy < (unsigned)HH && (unsigned)gx < (unsigned)WW)
            v = __ldg((const float4*)&src[((size_t)gy * WW + gx) * CIN + c4 * 4]);
        float* d = &s_in[(row * 32 + c4 * 4) * IN_COLS + col];
        d[0 * IN_COLS] = v.x;
        d[1 * IN_COLS] = v.y;
        d[2 * IN_COLS] = v.z;
        d[3 * IN_COLS] = v.w;
    }
}

// h tile loader from TRANSPOSED layout [f][y][x]: L1-bypassing float4 loads.
__device__ __forceinline__ void load_h_tile(
    float* __restrict__ s_in, const float* __restrict__ src,
    int ty0, int tx0, int tid)
{
    for (int j = tid; j < 18 * 32 * 8; j += 256) {
        int c4  = j & 7;
        int cin = (j >> 3) & 31;
        int row = j >> 8;
        int gy = ty0 + row - 1;
        int gx0 = tx0 + c4 * 4;
        float4 v = make_float4(0.f, 0.f, 0.f, 0.f);
        if ((unsigned)gy < (unsigned)HH)
            v = __ldcv((const float4*)&src[((size_t)cin * HH + gy) * WW + gx0]);
        float* d = &s_in[(row * 32 + cin) * IN_COLS + (c4 * 4 + 1)];
        d[0] = v.x; d[1] = v.y; d[2] = v.z; d[3] = v.w;
    }
    for (int j = tid; j < 18 * 32 * 2; j += 256) {
        int e   = j & 1;
        int cin = (j >> 1) & 31;
        int row = j >> 6;
        int gy = ty0 + row - 1;
        int gx = e ? (tx0 + 32) : (tx0 - 1);
        float v = 0.f;
        if ((unsigned)gy < (unsigned)HH && (unsigned)gx < (unsigned)WW)
            v = __ldcv(&src[((size_t)cin * HH + gy) * WW + gx]);
        s_in[(row * 32 + cin) * IN_COLS + (e ? 33 : 0)] = v;
    }
}

__global__ void bar_reset_kernel() {
    if (threadIdx.x < TT) g_bar[threadIdx.x] = 0u;
}

// ---------------------------------------------------------------------------
// Fully fused persistent ConvLSTM (R13 structure; only change vs R13:
// tap-pair double buffering -> 10 syncs/step instead of 18).
// grid 256 CTAs (2/SM), block 256, 2 px/thread.
// ---------------------------------------------------------------------------
__global__ void __launch_bounds__(256, 2) convlstm_persistent(
    const float* __restrict__ x, const float* __restrict__ Wx,
    const float* __restrict__ Wh, const float* __restrict__ b,
    const float* __restrict__ gamma, const float* __restrict__ beta,
    const float* __restrict__ mmean, const float* __restrict__ mvar,
    float* __restrict__ out)
{
    extern __shared__ float sm[];
    float* s_in   = sm;
    float* s_w    = sm + SIN_FLOATS;
    float* s_bias = sm + SIN_FLOATS + SWBUF_FLOATS;

    const int cta  = blockIdx.x;
    const int tile = cta & 7;
    const int fc   = (cta >> 3) & 3;
    const int bb   = cta >> 5;
    const int tx0 = (tile & 1) * TW;
    const int ty0 = (tile >> 1) * TH;
    const int tid = threadIdx.x;
    const int px = tid & 31, pr = tid >> 5;
    const int gx = tx0 + px;
    const int gy0 = ty0 + pr;

    // BN constants (loop-invariant)
    float inv[8], off[8];
#pragma unroll
    for (int j = 0; j < 8; j++) {
        int f = fc * 8 + j;
        inv[j] = gamma[f] * rsqrtf(mvar[f] + BN_EPS);
        off[j] = beta[f] - mmean[f] * inv[j];
    }
    // interleaved bias: s_bias[col] = b[(col>>3)*32 + fc*8 + (col&7)]
    if (tid < 32)
        s_bias[tid] = b[(tid >> 3) * 32 + fc * 8 + (tid & 7)];
    __syncthreads();

    for (int t = 0; t < TT; t++) {
        // init accumulators with bias (packed pairs from smem)
        ull acc0[16], acc1[16];
#pragma unroll
        for (int m = 0; m < 16; m++) {
            ull bv = *(const ull*)&s_bias[2 * m];
            acc0[m] = bv; acc1[m] = bv;
        }

        // ---- x contribution: conv(x_t, Wx) ----
        load_x_tile(s_in, x + (size_t)(bb * TT + t) * HH * WW * CIN, ty0, tx0, tid);
        conv_phase(Wx, s_in, s_w, fc, tid, pr, px, acc0, acc1);
        __syncthreads();

        // ---- h contribution: conv(h_{t-1}, Wh) (reuses s_in post-sync) ----
        if (t > 0) {
            const float* hin = g_h[(t + 1) & 1] + (size_t)bb * FF * HH * WW;
            load_h_tile(s_in, hin, ty0, tx0, tid);
            conv_phase(Wh, s_in, s_w, fc, tid, pr, px, acc0, acc1);
        }

        // ---- epilogue: gates, c/h update, BN, stores ----
        float a0[32], a1[32];
#pragma unroll
        for (int m = 0; m < 16; m++) {
            unpack2(acc0[m], a0[2 * m], a0[2 * m + 1]);
            unpack2(acc1[m], a1[2 * m], a1[2 * m + 1]);
        }

        float* hbase = g_h[t & 1] + (size_t)bb * FF * HH * WW;

#pragma unroll
        for (int p = 0; p < 2; p++) {
            const float* a = p ? a1 : a0;
            const int gy = gy0 + p * 8;
            const size_t pix   = (size_t)bb * HH * WW + (size_t)gy * WW + gx;
            const size_t frame = (size_t)(bb * TT + t) * HH * WW + (size_t)gy * WW + gx;
            float* cst = &g_c[pix * FF + fc * 8];
            float* op  = &out[frame * FF + fc * 8];

            float coldv[8] = {0,0,0,0,0,0,0,0};
            if (t > 0) {
                float4 c0 = ((const float4*)cst)[0];
                float4 c1 = ((const float4*)cst)[1];
                coldv[0]=c0.x; coldv[1]=c0.y; coldv[2]=c0.z; coldv[3]=c0.w;
                coldv[4]=c1.x; coldv[5]=c1.y; coldv[6]=c1.z; coldv[7]=c1.w;
            }

            float cv[8], hv[8], ov[8];
#pragma unroll
            for (int j = 0; j < 8; j++) {
                float gi = hsig(a[0 * 8 + j]);
                float gf = hsig(a[1 * 8 + j]);
                float gc = a[2 * 8 + j];
                float go = hsig(a[3 * 8 + j]);
                float cn = gf * coldv[j] + gi * tanhf(gc);
                float h  = go * tanhf(cn);
                cv[j] = cn; hv[j] = h;
                ov[j] = fmaf(h, inv[j], off[j]);
            }
            ((float4*)cst)[0] = make_float4(cv[0], cv[1], cv[2], cv[3]);
            ((float4*)cst)[1] = make_float4(cv[4], cv[5], cv[6], cv[7]);
#pragma unroll
            for (int j = 0; j < 8; j++) {
                int f = fc * 8 + j;
                hbase[((size_t)f * HH + gy) * WW + gx] = hv[j];
            }
            ((float4*)op)[0] = make_float4(ov[0], ov[1], ov[2], ov[3]);
            ((float4*)op)[1] = make_float4(ov[4], ov[5], ov[6], ov[7]);
        }

        // grid barrier: publish h_t before step t+1
        if (t < TT - 1) {
            __threadfence();
            __syncthreads();
            if (tid == 0) {
                atomicAdd(&g_bar[t], 1u);
                while (*((volatile unsigned*)&g_bar[t]) < (unsigned)LSTM_GRID)
                    __nanosleep(64);
            }
            __syncthreads();
            __threadfence();
        }
    }
}

// ===========================================================================
extern "C" void kernel_launch(void* const* d_in, const int* in_sizes, int n_in,
                              void* d_out, int out_size)
{
    const float* x     = (const float*)d_in[0];
    const float* Wx    = (const float*)d_in[1];
    const float* Wh    = (const float*)d_in[2];
    const float* b     = (const float*)d_in[3];
    const float* gamma = (const float*)d_in[4];
    const float* beta  = (const float*)d_in[5];
    const float* mmean = (const float*)d_in[6];
    const float* mvar  = (const float*)d_in[7];
    float* out = (float*)d_out;

    cudaFuncSetAttribute(convlstm_persistent,
        cudaFuncAttributeMaxDynamicSharedMemorySize, LS_SMEM);

    bar_reset_kernel<<<1, 32>>>();
    convlstm_persistent<<<LSTM_GRID, 256, LS_SMEM>>>(
        x, Wx, Wh, b, gamma, beta, mmean, mvar, out);
}